// round 7
// baseline (speedup 1.0000x reference)
#include <cuda_runtime.h>

#define NNODES 65536
#define NEDGES 524288
#define NGRAPH 128
#define NPG    512
#define EPG    4096
#define F_IN   128
#define H1D    64
#define H2D    128
#define NCLS   10
#define KSEL   410

// ---------------- scratch (static device globals; no allocation) -------------
__device__ __align__(16) int   g_cnt[NNODES];
__device__ __align__(16) int   g_fill[NNODES];
__device__ __align__(16) int   g_rowptr[NNODES];
__device__ __align__(16) float g_dis[NNODES];
__device__ __align__(16) int   g_csr[NEDGES];
__device__ __align__(16) float g_h1[NNODES * H1D];
__device__ __align__(16) float g_out1[NNODES * H1D];
__device__ __align__(16) float g_h2[NNODES * H2D];
__device__ __align__(16) float g_out2[NNODES * H2D];
__device__ __align__(16) float g_score[NNODES];
__device__ int g_is64;

// ---------------- structure kernels ----------------------------------------
__global__ void zero_kernel() {
    int i = blockIdx.x * blockDim.x + threadIdx.x;
    g_cnt[i] = 0;
    g_fill[i] = 0;
}

// edge_index may arrive as int64 (x64 mode) or int32 (default JAX). Node ids
// are < 2^16, so if int64 every odd 32-bit word is 0. OR a prefix to decide.
__global__ void detect_kernel(const int* __restrict__ ei) {
    __shared__ int sred[256];
    int t = threadIdx.x;
    int v = 0;
    for (int i = t; i < 1024; i += 256) v |= ei[2 * i + 1];
    sred[t] = v;
    __syncthreads();
    for (int o = 128; o > 0; o >>= 1) {
        if (t < o) sred[t] |= sred[t + o];
        __syncthreads();
    }
    if (t == 0) g_is64 = (sred[0] == 0) ? 1 : 0;
}

__global__ void count_kernel(const int* __restrict__ ei) {
    int i = blockIdx.x * blockDim.x + threadIdx.x;   // exactly NEDGES threads
    int d = g_is64 ? ei[2 * (NEDGES + i)] : ei[NEDGES + i];
    atomicAdd(&g_cnt[d], 1);
}

// per-graph exclusive scan of edge counts -> CSR row pointers; also dis = rsqrt(deg)
__global__ void scan_kernel() {
    __shared__ int s[NPG];
    int b = blockIdx.x, t = threadIdx.x;
    int node = b * NPG + t;
    int c = g_cnt[node];
    s[t] = c;
    __syncthreads();
    for (int off = 1; off < NPG; off <<= 1) {
        int v = (t >= off) ? s[t - off] : 0;
        __syncthreads();
        s[t] += v;
        __syncthreads();
    }
    g_rowptr[node] = b * EPG + s[t] - c;
    g_dis[node] = rsqrtf((float)(c + 1));   // +1 self-loop; deg >= 1 always
}

__global__ void scatter_kernel(const int* __restrict__ ei) {
    int i = blockIdx.x * blockDim.x + threadIdx.x;   // exactly NEDGES threads
    int sv, dv;
    if (g_is64) { sv = ei[2 * i]; dv = ei[2 * (NEDGES + i)]; }
    else        { sv = ei[i];     dv = ei[NEDGES + i]; }
    int p = atomicAdd(&g_fill[dv], 1);
    g_csr[g_rowptr[dv] + p] = sv;
}

// ---------------- GEMM 1: h1[65536,64] = x[65536,128] @ W1[128,64] ----------
// BM=128, BN=64, BK=32, 256 threads, 8x4 microtile.
__global__ void __launch_bounds__(256) gemm1_kernel(const float* __restrict__ x,
                                                    const float* __restrict__ W) {
    __shared__ __align__(16) float xs[32 * 132];   // [k][r], pitch 132
    __shared__ __align__(16) float ws[32 * 64];    // [k][c]
    int t = threadIdx.x;
    int tx = t & 15, ty = t >> 4;
    int row0 = blockIdx.x << 7;
    float acc[8][4];
#pragma unroll
    for (int i = 0; i < 8; i++)
#pragma unroll
        for (int j = 0; j < 4; j++) acc[i][j] = 0.f;

    for (int kt = 0; kt < 128; kt += 32) {
#pragma unroll
        for (int i = 0; i < 16; i++) {
            int idx = t + (i << 8);
            int r = idx >> 5, k = idx & 31;
            xs[k * 132 + r] = x[(row0 + r) * F_IN + kt + k];
        }
#pragma unroll
        for (int i = 0; i < 8; i++) {
            int idx = t + (i << 8);
            int k = idx >> 6, c = idx & 63;
            ws[k * 64 + c] = W[(kt + k) * H1D + c];
        }
        __syncthreads();
#pragma unroll
        for (int k = 0; k < 32; k++) {
            float4 a0 = *(const float4*)&xs[k * 132 + ty * 8];
            float4 a1 = *(const float4*)&xs[k * 132 + ty * 8 + 4];
            float4 bb = *(const float4*)&ws[k * 64 + tx * 4];
            float av[8] = {a0.x, a0.y, a0.z, a0.w, a1.x, a1.y, a1.z, a1.w};
            float bv[4] = {bb.x, bb.y, bb.z, bb.w};
#pragma unroll
            for (int i = 0; i < 8; i++)
#pragma unroll
                for (int j = 0; j < 4; j++) acc[i][j] += av[i] * bv[j];
        }
        __syncthreads();
    }
#pragma unroll
    for (int i = 0; i < 8; i++) {
        float4 v = make_float4(acc[i][0], acc[i][1], acc[i][2], acc[i][3]);
        *(float4*)&g_h1[(row0 + ty * 8 + i) * H1D + tx * 4] = v;
    }
}

// ---------------- aggregation 1 (+bias +ReLU), warp per node ----------------
__global__ void __launch_bounds__(256) agg1_kernel(const float* __restrict__ b1) {
    int node = (blockIdx.x * 256 + threadIdx.x) >> 5;   // exactly NNODES warps
    int lane = threadIdx.x & 31;
    float di = g_dis[node];
    const float* hr = g_h1 + node * H1D;
    float d2 = di * di;
    float a0 = d2 * hr[lane];
    float a1 = d2 * hr[lane + 32];
    int st = g_rowptr[node], c = g_cnt[node];
    int e = 0;
    for (; e + 1 < c; e += 2) {
        int s0 = g_csr[st + e], s1 = g_csr[st + e + 1];
        float w0 = di * g_dis[s0], w1 = di * g_dis[s1];
        const float* p0 = g_h1 + s0 * H1D;
        const float* p1 = g_h1 + s1 * H1D;
        a0 += w0 * p0[lane]      + w1 * p1[lane];
        a1 += w0 * p0[lane + 32] + w1 * p1[lane + 32];
    }
    if (e < c) {
        int s0 = g_csr[st + e];
        float w0 = di * g_dis[s0];
        const float* p0 = g_h1 + s0 * H1D;
        a0 += w0 * p0[lane];
        a1 += w0 * p0[lane + 32];
    }
    g_out1[node * H1D + lane]      = fmaxf(a0 + b1[lane], 0.f);
    g_out1[node * H1D + lane + 32] = fmaxf(a1 + b1[lane + 32], 0.f);
}

// ---------------- GEMM 2: h2[65536,128] = out1[65536,64] @ W2[64,128] -------
// BM=128, BN=128, BK=32, 256 threads, 8x8 microtile.
__global__ void __launch_bounds__(256) gemm2_kernel(const float* __restrict__ W) {
    __shared__ __align__(16) float xs[32 * 132];
    __shared__ __align__(16) float ws[32 * 128];
    int t = threadIdx.x;
    int tx = t & 15, ty = t >> 4;
    int row0 = blockIdx.x << 7;
    float acc[8][8];
#pragma unroll
    for (int i = 0; i < 8; i++)
#pragma unroll
        for (int j = 0; j < 8; j++) acc[i][j] = 0.f;

    for (int kt = 0; kt < 64; kt += 32) {
#pragma unroll
        for (int i = 0; i < 16; i++) {
            int idx = t + (i << 8);
            int r = idx >> 5, k = idx & 31;
            xs[k * 132 + r] = g_out1[(row0 + r) * H1D + kt + k];
        }
#pragma unroll
        for (int i = 0; i < 16; i++) {
            int idx = t + (i << 8);
            int k = idx >> 7, c = idx & 127;
            ws[k * 128 + c] = W[(kt + k) * H2D + c];
        }
        __syncthreads();
#pragma unroll
        for (int k = 0; k < 32; k++) {
            float4 a0 = *(const float4*)&xs[k * 132 + ty * 8];
            float4 a1 = *(const float4*)&xs[k * 132 + ty * 8 + 4];
            float4 b0 = *(const float4*)&ws[k * 128 + tx * 8];
            float4 b1 = *(const float4*)&ws[k * 128 + tx * 8 + 4];
            float av[8] = {a0.x, a0.y, a0.z, a0.w, a1.x, a1.y, a1.z, a1.w};
            float bv[8] = {b0.x, b0.y, b0.z, b0.w, b1.x, b1.y, b1.z, b1.w};
#pragma unroll
            for (int i = 0; i < 8; i++)
#pragma unroll
                for (int j = 0; j < 8; j++) acc[i][j] += av[i] * bv[j];
        }
        __syncthreads();
    }
#pragma unroll
    for (int i = 0; i < 8; i++) {
        float4 v0 = make_float4(acc[i][0], acc[i][1], acc[i][2], acc[i][3]);
        float4 v1 = make_float4(acc[i][4], acc[i][5], acc[i][6], acc[i][7]);
        *(float4*)&g_h2[(row0 + ty * 8 + i) * H2D + tx * 8]     = v0;
        *(float4*)&g_h2[(row0 + ty * 8 + i) * H2D + tx * 8 + 4] = v1;
    }
}

// ---------------- aggregation 2 (+bias +ReLU +pool score), warp per node ----
__global__ void __launch_bounds__(256) agg2_kernel(const float* __restrict__ b2,
                                                   const float* __restrict__ pw) {
    int node = (blockIdx.x * 256 + threadIdx.x) >> 5;
    int lane = threadIdx.x & 31;
    float di = g_dis[node];
    const float* hr = g_h2 + node * H2D;
    float d2 = di * di;
    float a0 = d2 * hr[lane];
    float a1 = d2 * hr[lane + 32];
    float a2 = d2 * hr[lane + 64];
    float a3 = d2 * hr[lane + 96];
    int st = g_rowptr[node], c = g_cnt[node];
    int e = 0;
    for (; e + 1 < c; e += 2) {
        int s0 = g_csr[st + e], s1 = g_csr[st + e + 1];
        float w0 = di * g_dis[s0], w1 = di * g_dis[s1];
        const float* p0 = g_h2 + s0 * H2D;
        const float* p1 = g_h2 + s1 * H2D;
        a0 += w0 * p0[lane]      + w1 * p1[lane];
        a1 += w0 * p0[lane + 32] + w1 * p1[lane + 32];
        a2 += w0 * p0[lane + 64] + w1 * p1[lane + 64];
        a3 += w0 * p0[lane + 96] + w1 * p1[lane + 96];
    }
    if (e < c) {
        int s0 = g_csr[st + e];
        float w0 = di * g_dis[s0];
        const float* p0 = g_h2 + s0 * H2D;
        a0 += w0 * p0[lane];
        a1 += w0 * p0[lane + 32];
        a2 += w0 * p0[lane + 64];
        a3 += w0 * p0[lane + 96];
    }
    float o0 = fmaxf(a0 + b2[lane], 0.f);
    float o1 = fmaxf(a1 + b2[lane + 32], 0.f);
    float o2 = fmaxf(a2 + b2[lane + 64], 0.f);
    float o3 = fmaxf(a3 + b2[lane + 96], 0.f);
    g_out2[node * H2D + lane]      = o0;
    g_out2[node * H2D + lane + 32] = o1;
    g_out2[node * H2D + lane + 64] = o2;
    g_out2[node * H2D + lane + 96] = o3;
    // TopK score = (x . w) / ||w||
    float pw0 = pw[lane], pw1 = pw[lane + 32], pw2 = pw[lane + 64], pw3 = pw[lane + 96];
    float dot = o0 * pw0 + o1 * pw1 + o2 * pw2 + o3 * pw3;
    float nw  = pw0 * pw0 + pw1 * pw1 + pw2 * pw2 + pw3 * pw3;
#pragma unroll
    for (int o = 16; o > 0; o >>= 1) {
        dot += __shfl_xor_sync(0xffffffffu, dot, o);
        nw  += __shfl_xor_sync(0xffffffffu, nw, o);
    }
    if (lane == 0) g_score[node] = dot * rsqrtf(nw);
}

// ---------------- per-graph: TopK sort, gated max pool, FC, log_softmax -----
__global__ void __launch_bounds__(512) final_kernel(const float* __restrict__ fcW,
                                                    const float* __restrict__ fcb,
                                                    float* __restrict__ out) {
    __shared__ float skey[NPG];
    __shared__ int   sidx[NPG];
    __shared__ float partial[NPG];
    __shared__ float gfeat[H2D];
    __shared__ float logits[NCLS];
    __shared__ float s_lse;
    int b = blockIdx.x, t = threadIdx.x;
    skey[t] = g_score[b * NPG + t];
    sidx[t] = t;
    // bitonic sort, descending, tie-break: smaller index ranks higher (lax.top_k)
    for (int k = 2; k <= NPG; k <<= 1) {
        for (int j = k >> 1; j > 0; j >>= 1) {
            __syncthreads();
            int ixj = t ^ j;
            if (ixj > t) {
                float ka = skey[t], kb = skey[ixj];
                int ia = sidx[t], ib = sidx[ixj];
                bool bGreater = (kb > ka) || (kb == ka && ib < ia);
                bool desc = ((t & k) == 0);
                if (desc == bGreater) {
                    skey[t] = kb; skey[ixj] = ka;
                    sidx[t] = ib; sidx[ixj] = ia;
                }
            }
        }
    }
    __syncthreads();
    float gate = (t < KSEL) ? tanhf(skey[t]) : 0.f;
    __syncthreads();
    if (t < KSEL) skey[t] = gate;
    __syncthreads();
    // gated max over selected nodes: 4 partitions x 128 features
    {
        int f = t & 127, part = t >> 7;
        float m = -3.4e38f;
        const float* base = g_out2 + (size_t)b * NPG * H2D;
#pragma unroll 4
        for (int kk = part; kk < KSEL; kk += 4) {
            int node = sidx[kk];
            m = fmaxf(m, base[node * H2D + f] * skey[kk]);
        }
        partial[t] = m;
    }
    __syncthreads();
    if (t < H2D)
        gfeat[t] = fmaxf(fmaxf(partial[t], partial[t + 128]),
                         fmaxf(partial[t + 256], partial[t + 384]));
    __syncthreads();
    // FC: one warp per class
    if (t < NCLS * 32) {
        int c = t >> 5, lane = t & 31;
        float acc = 0.f;
        for (int f = lane; f < H2D; f += 32) acc += gfeat[f] * fcW[f * NCLS + c];
#pragma unroll
        for (int o = 16; o > 0; o >>= 1) acc += __shfl_down_sync(0xffffffffu, acc, o);
        if (lane == 0) logits[c] = acc + fcb[c];
    }
    __syncthreads();
    if (t == 0) {
        float mx = -3.4e38f;
        for (int c = 0; c < NCLS; c++) mx = fmaxf(mx, logits[c]);
        float s = 0.f;
        for (int c = 0; c < NCLS; c++) s += expf(logits[c] - mx);
        s_lse = mx + logf(s);
    }
    __syncthreads();
    if (t < NCLS) out[b * NCLS + t] = logits[t] - s_lse;
}

// ---------------- launch -----------------------------------------------------
extern "C" void kernel_launch(void* const* d_in, const int* in_sizes, int n_in,
                              void* d_out, int out_size) {
    const float* x    = (const float*)d_in[0];
    const int*   ei   = (const int*)d_in[1];   // int32 view; int64 handled via g_is64
    const float* W1   = (const float*)d_in[3];
    const float* b1   = (const float*)d_in[4];
    const float* W2   = (const float*)d_in[5];
    const float* b2   = (const float*)d_in[6];
    const float* pw   = (const float*)d_in[7];
    const float* fcW  = (const float*)d_in[8];
    const float* fcb  = (const float*)d_in[9];
    float* out = (float*)d_out;

    zero_kernel<<<NNODES / 256, 256>>>();
    detect_kernel<<<1, 256>>>(ei);
    count_kernel<<<NEDGES / 256, 256>>>(ei);
    scan_kernel<<<NGRAPH, NPG>>>();
    scatter_kernel<<<NEDGES / 256, 256>>>(ei);

    gemm1_kernel<<<NNODES / 128, 256>>>(x, W1);
    agg1_kernel<<<NNODES / 8, 256>>>(b1);
    gemm2_kernel<<<NNODES / 128, 256>>>(W2);
    agg2_kernel<<<NNODES / 8, 256>>>(b2, pw);
    final_kernel<<<NGRAPH, NPG>>>(fcW, fcb, out);
}